// round 14
// baseline (speedup 1.0000x reference)
#include <cuda_runtime.h>

#define N_NODES 100000
#define E_EDGES 1600000
#define NEG 0.2f
#define EPSV 1e-16f
#define CAP 64        // bucket capacity; deg ~ Poisson(16), P(>=64) ~ 1e-19

// Scratch (no allocs allowed)
__device__ int   g_cnt[N_NODES];            // in-degree / scatter cursor
__device__ int   g_adj[N_NODES * CAP];      // src ids, grouped by dst
__device__ float g_h2[N_NODES];             // layer-2 node features
__device__ float g_S1[8];                   // sum_c W1[h,c]*att_src1[h,c]
__device__ float g_D1[8];
__device__ float g_sc2[3];                  // att_src2, att_dst2, b2

// ---- zero cursors + per-head logit coefficients ------------------------
__global__ void k_zero(const float* __restrict__ W1,
                       const float* __restrict__ as1,
                       const float* __restrict__ ad1,
                       const float* __restrict__ as2,
                       const float* __restrict__ ad2,
                       const float* __restrict__ b2) {
    int i = blockIdx.x * blockDim.x + threadIdx.x;
    if (i < N_NODES) g_cnt[i] = 0;
    if (blockIdx.x == 0) {
        int h = threadIdx.x;
        if (h < 8) {
            float s = 0.f, d = 0.f;
            #pragma unroll
            for (int c = 0; c < 16; c++) {
                float w = W1[h * 16 + c];
                s += w * as1[h * 16 + c];
                d += w * ad1[h * 16 + c];
            }
            g_S1[h] = s;
            g_D1[h] = d;
        }
        if (h == 8) { g_sc2[0] = as2[0]; g_sc2[1] = ad2[0]; g_sc2[2] = b2[0]; }
    }
}

// ---- bucket scatter: adjacency grouped by dst (single 4B store/edge) ---
__global__ void __launch_bounds__(256)
k_scatter(const int* __restrict__ src, const int* __restrict__ dst) {
    int i = blockIdx.x * blockDim.x + threadIdx.x;
    if (i >= E_EDGES) return;
    int d = dst[i];
    int pos = atomicAdd(&g_cnt[d], 1);
    if (pos < CAP) g_adj[d * CAP + pos] = src[i];
}

// ---- layer-1 gather + softmax + elu + layer-2 projection ---------------
// 4 lanes per node: edges split across lanes, shfl-combine, epilogue split.
__global__ void __launch_bounds__(256)
k_g1(const float* __restrict__ x,
     const float* __restrict__ W1, const float* __restrict__ b1,
     const float* __restrict__ W2) {
    __shared__ float sW1[128], sb1[128], sW2[128], sS[8], sD[8];
    int t = threadIdx.x;
    if (t < 128) { sW1[t] = W1[t]; sb1[t] = b1[t]; sW2[t] = W2[t]; }
    if (t < 8)   { sS[t] = g_S1[t]; sD[t] = g_D1[t]; }
    __syncthreads();
    int gid  = (blockIdx.x * 256 + t) >> 2;   // node
    int lane = t & 3;
    if (gid >= N_NODES) return;

    float xd = __ldg(x + gid);
    float num[8], den[8], ed[8];
    #pragma unroll
    for (int h = 0; h < 8; h++) {
        ed[h] = xd * sD[h];
        if (lane == 0) {                          // self loop on lane 0 only
            float e = fmaf(xd, sS[h], ed[h]);
            e = e > 0.f ? e : NEG * e;
            float p = __expf(e);
            num[h] = p * xd;
            den[h] = p;
        } else { num[h] = 0.f; den[h] = 0.f; }
    }
    int deg = min(g_cnt[gid], CAP);
    const int* row = g_adj + (size_t)gid * CAP;
    for (int j = lane; j < deg; j += 4) {
        float xs = __ldg(x + row[j]);             // x is 400KB -> cache-resident
        #pragma unroll
        for (int h = 0; h < 8; h++) {
            float e = fmaf(xs, sS[h], ed[h]);
            e = e > 0.f ? e : NEG * e;
            float p = __expf(e);                  // no max-shift (bounded scores)
            num[h] = fmaf(p, xs, num[h]);
            den[h] += p;
        }
    }
    // combine partials across the 4 lanes
    #pragma unroll
    for (int h = 0; h < 8; h++) {
        num[h] += __shfl_xor_sync(0xFFFFFFFF, num[h], 1);
        num[h] += __shfl_xor_sync(0xFFFFFFFF, num[h], 2);
        den[h] += __shfl_xor_sync(0xFFFFFFFF, den[h], 1);
        den[h] += __shfl_xor_sync(0xFFFFFFFF, den[h], 2);
    }
    // epilogue split: each lane does 2 heads (32 elu terms)
    float acc = 0.f;
    #pragma unroll
    for (int hh = 0; hh < 2; hh++) {
        int h = lane * 2 + hh;
        float th = __fdividef(num[h], den[h] + EPSV);
        #pragma unroll
        for (int c = 0; c < 16; c++) {
            int k = h * 16 + c;
            float u = fmaf(th, sW1[k], sb1[k]);
            u = u > 0.f ? u : __expf(u) - 1.f;    // elu
            acc = fmaf(u, sW2[k], acc);
        }
    }
    acc += __shfl_xor_sync(0xFFFFFFFF, acc, 1);
    acc += __shfl_xor_sync(0xFFFFFFFF, acc, 2);
    if (lane == 0) g_h2[gid] = acc;
}

// ---- layer-2 gather -> output. 8 lanes per node. -----------------------
__global__ void __launch_bounds__(256)
k_g2(float* __restrict__ out) {
    int t = threadIdx.x;
    int gid  = (blockIdx.x * 256 + t) >> 3;
    int lane = t & 7;
    if (gid >= N_NODES) return;
    float a2 = g_sc2[0], bb = g_sc2[1], c2 = g_sc2[2];
    float hd = g_h2[gid];
    float hdb = hd * bb;
    float num = 0.f, den = 0.f;
    if (lane == 0) {                              // self loop
        float e = fmaf(hd, a2, hdb);
        e = e > 0.f ? e : NEG * e;
        float p = __expf(e);
        num = p * hd;
        den = p;
    }
    int deg = min(g_cnt[gid], CAP);
    const int* row = g_adj + (size_t)gid * CAP;
    for (int j = lane; j < deg; j += 8) {
        float hs = g_h2[row[j]];
        float e2 = fmaf(hs, a2, hdb);
        e2 = e2 > 0.f ? e2 : NEG * e2;
        float q = __expf(e2);
        num = fmaf(q, hs, num);
        den += q;
    }
    num += __shfl_xor_sync(0xFFFFFFFF, num, 1);
    num += __shfl_xor_sync(0xFFFFFFFF, num, 2);
    num += __shfl_xor_sync(0xFFFFFFFF, num, 4);
    den += __shfl_xor_sync(0xFFFFFFFF, den, 1);
    den += __shfl_xor_sync(0xFFFFFFFF, den, 2);
    den += __shfl_xor_sync(0xFFFFFFFF, den, 4);
    if (lane == 0) out[gid] = __fdividef(num, den + EPSV) + c2;
}

extern "C" void kernel_launch(void* const* d_in, const int* in_sizes, int n_in,
                              void* d_out, int out_size) {
    const float* x   = (const float*)d_in[0];
    const int*   ei  = (const int*)d_in[1];   // int64 in reference -> int32 in harness
    const float* W1  = (const float*)d_in[2];
    const float* as1 = (const float*)d_in[3];
    const float* ad1 = (const float*)d_in[4];
    const float* b1  = (const float*)d_in[5];
    const float* W2  = (const float*)d_in[6];
    const float* as2 = (const float*)d_in[7];
    const float* ad2 = (const float*)d_in[8];
    const float* b2  = (const float*)d_in[9];
    float* out = (float*)d_out;

    const int* src = ei;
    const int* dst = ei + E_EDGES;

    k_zero<<<(N_NODES + 255) / 256, 256>>>(W1, as1, ad1, as2, ad2, b2);
    k_scatter<<<(E_EDGES + 255) / 256, 256>>>(src, dst);
    k_g1<<<(N_NODES * 4 + 255) / 256, 256>>>(x, W1, b1, W2);
    k_g2<<<(N_NODES * 8 + 255) / 256, 256>>>(out);
}

// round 16
// speedup vs baseline: 1.4247x; 1.4247x over previous
#include <cuda_runtime.h>

#define N_NODES 100000
#define E_EDGES 1600000
#define NEG 0.2f
#define EPSV 1e-16f
#define CAP 64        // bucket capacity; deg ~ Poisson(16), P(>=64) ~ 1e-19

// Scratch (no allocs allowed)
__device__ int  g_cnt[N_NODES];             // in-degree / scatter cursor
__device__ int2 g_adj2[N_NODES * CAP];      // (src, bitcast x[src]) grouped by dst
__device__ float g_h2[N_NODES];             // layer-2 node features
__device__ float g_S1[8];                   // sum_c W1[h,c]*att_src1[h,c]
__device__ float g_D1[8];
__device__ float g_sc2[3];                  // att_src2, att_dst2, b2

// ---- zero cursors + per-head logit coefficients ------------------------
__global__ void k_zero(const float* __restrict__ W1,
                       const float* __restrict__ as1,
                       const float* __restrict__ ad1,
                       const float* __restrict__ as2,
                       const float* __restrict__ ad2,
                       const float* __restrict__ b2) {
    int i = blockIdx.x * blockDim.x + threadIdx.x;
    if (i < N_NODES) g_cnt[i] = 0;
    if (blockIdx.x == 0) {
        int h = threadIdx.x;
        if (h < 8) {
            float s = 0.f, d = 0.f;
            #pragma unroll
            for (int c = 0; c < 16; c++) {
                float w = W1[h * 16 + c];
                s += w * as1[h * 16 + c];
                d += w * ad1[h * 16 + c];
            }
            g_S1[h] = s;
            g_D1[h] = d;
        }
        if (h == 8) { g_sc2[0] = as2[0]; g_sc2[1] = ad2[0]; g_sc2[2] = b2[0]; }
    }
}

// ---- bucket scatter: one 8B (src, x[src]) store per edge ---------------
__global__ void __launch_bounds__(256)
k_scatter(const int* __restrict__ src, const int* __restrict__ dst,
          const float* __restrict__ x) {
    int i = blockIdx.x * blockDim.x + threadIdx.x;
    if (i >= E_EDGES) return;
    int d = dst[i], s = src[i];
    float xs = __ldg(x + s);                  // x = 400KB, cache-resident
    int pos = atomicAdd(&g_cnt[d], 1);
    if (pos < CAP) g_adj2[d * CAP + pos] = make_int2(s, __float_as_int(xs));
}

// ---- layer-1 gather + softmax + elu + layer-2 projection ---------------
// 4 lanes/node; each lane reads int4 = 2 packed (src,x) entries per trip.
__global__ void __launch_bounds__(256)
k_g1(const float* __restrict__ x,
     const float* __restrict__ W1, const float* __restrict__ b1,
     const float* __restrict__ W2) {
    __shared__ float sW1[128], sb1[128], sW2[128], sS[8], sD[8];
    int t = threadIdx.x;
    if (t < 128) { sW1[t] = W1[t]; sb1[t] = b1[t]; sW2[t] = W2[t]; }
    if (t < 8)   { sS[t] = g_S1[t]; sD[t] = g_D1[t]; }
    __syncthreads();
    int gid  = (blockIdx.x * 256 + t) >> 2;   // node
    int lane = t & 3;
    if (gid >= N_NODES) return;

    float xd = __ldg(x + gid);
    int deg = g_cnt[gid];
    float num[8], den[8], ed[8];
    #pragma unroll
    for (int h = 0; h < 8; h++) {
        ed[h] = xd * sD[h];
        num[h] = 0.f; den[h] = 0.f;
    }
    if (lane == 0) {                          // self loop + odd tail on lane 0
        float xt[2]; int nt = 1;
        xt[0] = xd;
        if (deg & 1)
            xt[nt++] = __int_as_float(g_adj2[(size_t)gid * CAP + deg - 1].y);
        for (int q = 0; q < nt; q++) {
            float xs = xt[q];
            #pragma unroll
            for (int h = 0; h < 8; h++) {
                float e = fmaf(xs, sS[h], ed[h]);
                e = e > 0.f ? e : NEG * e;
                float p = __expf(e);
                num[h] = fmaf(p, xs, num[h]);
                den[h] += p;
            }
        }
    }
    int npair = deg >> 1;
    const int4* row4 = (const int4*)(g_adj2 + (size_t)gid * CAP);
    for (int p = lane; p < npair; p += 4) {
        int4 v = row4[p];                     // 2 edges, ONE load, no chain
        float x0 = __int_as_float(v.y);
        float x1 = __int_as_float(v.w);
        #pragma unroll
        for (int h = 0; h < 8; h++) {
            float e0 = fmaf(x0, sS[h], ed[h]);
            float e1 = fmaf(x1, sS[h], ed[h]);
            e0 = e0 > 0.f ? e0 : NEG * e0;
            e1 = e1 > 0.f ? e1 : NEG * e1;
            float p0 = __expf(e0), p1 = __expf(e1);  // no max-shift (bounded)
            num[h] = fmaf(p0, x0, num[h]);
            num[h] = fmaf(p1, x1, num[h]);
            den[h] += p0 + p1;
        }
    }
    #pragma unroll
    for (int h = 0; h < 8; h++) {
        num[h] += __shfl_xor_sync(0xFFFFFFFF, num[h], 1);
        num[h] += __shfl_xor_sync(0xFFFFFFFF, num[h], 2);
        den[h] += __shfl_xor_sync(0xFFFFFFFF, den[h], 1);
        den[h] += __shfl_xor_sync(0xFFFFFFFF, den[h], 2);
    }
    // epilogue split: each lane does 2 heads (32 elu terms)
    float acc = 0.f;
    #pragma unroll
    for (int hh = 0; hh < 2; hh++) {
        int h = lane * 2 + hh;
        float th = __fdividef(num[h], den[h] + EPSV);
        #pragma unroll
        for (int c = 0; c < 16; c++) {
            int k = h * 16 + c;
            float u = fmaf(th, sW1[k], sb1[k]);
            u = u > 0.f ? u : __expf(u) - 1.f;    // elu
            acc = fmaf(u, sW2[k], acc);
        }
    }
    acc += __shfl_xor_sync(0xFFFFFFFF, acc, 1);
    acc += __shfl_xor_sync(0xFFFFFFFF, acc, 2);
    if (lane == 0) g_h2[gid] = acc;
}

// ---- layer-2 gather -> output. 4 lanes/node, int4 = 2 ids per trip. ----
__global__ void __launch_bounds__(256)
k_g2(float* __restrict__ out) {
    int t = threadIdx.x;
    int gid  = (blockIdx.x * 256 + t) >> 2;
    int lane = t & 3;
    if (gid >= N_NODES) return;
    float a2 = g_sc2[0], bb = g_sc2[1], c2 = g_sc2[2];
    float hd = g_h2[gid];
    float hdb = hd * bb;
    int deg = g_cnt[gid];
    float num = 0.f, den = 0.f;
    if (lane == 0) {                              // self loop + odd tail
        float ht[2]; int nt = 1;
        ht[0] = hd;
        if (deg & 1)
            ht[nt++] = g_h2[g_adj2[(size_t)gid * CAP + deg - 1].x];
        for (int q = 0; q < nt; q++) {
            float hs = ht[q];
            float e = fmaf(hs, a2, hdb);
            e = e > 0.f ? e : NEG * e;
            float p = __expf(e);
            num = fmaf(p, hs, num);
            den += p;
        }
    }
    int npair = deg >> 1;
    const int4* row4 = (const int4*)(g_adj2 + (size_t)gid * CAP);
    for (int p = lane; p < npair; p += 4) {
        int4 v = row4[p];
        float h0 = g_h2[v.x];
        float h1 = g_h2[v.z];
        float e0 = fmaf(h0, a2, hdb);
        float e1 = fmaf(h1, a2, hdb);
        e0 = e0 > 0.f ? e0 : NEG * e0;
        e1 = e1 > 0.f ? e1 : NEG * e1;
        float q0 = __expf(e0), q1 = __expf(e1);
        num = fmaf(q0, h0, num);
        num = fmaf(q1, h1, num);
        den += q0 + q1;
    }
    num += __shfl_xor_sync(0xFFFFFFFF, num, 1);
    num += __shfl_xor_sync(0xFFFFFFFF, num, 2);
    den += __shfl_xor_sync(0xFFFFFFFF, den, 1);
    den += __shfl_xor_sync(0xFFFFFFFF, den, 2);
    if (lane == 0) out[gid] = __fdividef(num, den + EPSV) + c2;
}

extern "C" void kernel_launch(void* const* d_in, const int* in_sizes, int n_in,
                              void* d_out, int out_size) {
    const float* x   = (const float*)d_in[0];
    const int*   ei  = (const int*)d_in[1];   // int64 in reference -> int32 in harness
    const float* W1  = (const float*)d_in[2];
    const float* as1 = (const float*)d_in[3];
    const float* ad1 = (const float*)d_in[4];
    const float* b1  = (const float*)d_in[5];
    const float* W2  = (const float*)d_in[6];
    const float* as2 = (const float*)d_in[7];
    const float* ad2 = (const float*)d_in[8];
    const float* b2  = (const float*)d_in[9];
    float* out = (float*)d_out;

    const int* src = ei;
    const int* dst = ei + E_EDGES;

    k_zero<<<(N_NODES + 255) / 256, 256>>>(W1, as1, ad1, as2, ad2, b2);
    k_scatter<<<(E_EDGES + 255) / 256, 256>>>(src, dst, x);
    k_g1<<<(N_NODES * 4 + 255) / 256, 256>>>(x, W1, b1, W2);
    k_g2<<<(N_NODES * 4 + 255) / 256, 256>>>(out);
}